// round 1
// baseline (speedup 1.0000x reference)
#include <cuda_runtime.h>

// Problem constants
#define TB 2
#define TH 16
#define TS 2048
#define TD 64
#define TDK 128          // combined head dim [Q|Qpos]
#define BQ 128           // q rows per CTA
#define BK 64            // kv rows per tile
#define NT 256           // threads per block

// Shared-memory pitches (floats)
#define QP 132           // sQ  [BQ][QP]   row-major, 16B-aligned rows
#define KTP 68           // sKT [TDK][KTP] k-major (transposed K)
#define STP 129          // staging [BK][STP] -> conflict-free transpose
#define VP 68            // sV  [BK][VP]
#define PP 68            // sP  [BQ][PP]

#define SQ_SZ  (BQ*QP)          // 16896
#define SKT_SZ (TDK*KTP)        // 8704
#define STG_SZ (BK*STP)         // 8256
#define SV_SZ  (BK*VP)          // 4352
#define SP_SZ  (BQ*PP)          // 8704
#define SM_FLOATS (SQ_SZ + SKT_SZ + STG_SZ + SV_SZ + SP_SZ)  // 46912 -> 187648 B

__device__ __forceinline__ unsigned long long pk2(float x, float y) {
    unsigned long long r;
    asm("mov.b64 %0, {%1, %2};" : "=l"(r) : "f"(x), "f"(y));
    return r;
}
__device__ __forceinline__ void upk2(unsigned long long v, float& x, float& y) {
    asm("mov.b64 {%0, %1}, %2;" : "=f"(x), "=f"(y) : "l"(v));
}
__device__ __forceinline__ unsigned long long fma2(unsigned long long a,
                                                   unsigned long long b,
                                                   unsigned long long c) {
    unsigned long long d;
    asm("fma.rn.f32x2 %0, %1, %2, %3;" : "=l"(d) : "l"(a), "l"(b), "l"(c));
    return d;
}
__device__ __forceinline__ unsigned long long mul2(unsigned long long a,
                                                   unsigned long long b) {
    unsigned long long d;
    asm("mul.rn.f32x2 %0, %1, %2;" : "=l"(d) : "l"(a), "l"(b));
    return d;
}

__global__ __launch_bounds__(NT, 1)
void sdpa_flash_f32x2_kernel(const float* __restrict__ Qg,
                             const float* __restrict__ Kg,
                             const float* __restrict__ Vg,
                             const float* __restrict__ Qpg,
                             const float* __restrict__ Kpg,
                             float* __restrict__ Og)
{
    extern __shared__ float sm[];
    float* sQ  = sm;
    float* sKT = sQ  + SQ_SZ;
    float* stg = sKT + SKT_SZ;
    float* sV  = stg + STG_SZ;
    float* sP  = sV  + SV_SZ;

    const int tid = threadIdx.x;
    const int tx  = tid & 15;   // 16 column-groups of 4
    const int ty  = tid >> 4;   // 16 row-groups of 8
    const int bh  = blockIdx.y;
    const int q0  = blockIdx.x * BQ;

    const size_t bh_off = (size_t)bh * TS * TD;
    const float* Qb  = Qg  + bh_off;
    const float* Qpb = Qpg + bh_off;
    const float* Kb  = Kg  + bh_off;
    const float* Kpb = Kpg + bh_off;
    const float* Vb  = Vg  + bh_off;

    // ---- Load Q tile (BQ x TDK), pre-scaled by 1/sqrt(64) ----
    const float scale = 0.125f;
    #pragma unroll
    for (int it = 0; it < (BQ * TDK / 4) / NT; it++) {   // 16 iters
        int idx4 = tid + it * NT;
        int r = idx4 >> 5;            // 32 float4 per row
        int d = (idx4 & 31) << 2;
        const float* src = (d < TD) ? (Qb  + (size_t)(q0 + r) * TD + d)
                                    : (Qpb + (size_t)(q0 + r) * TD + (d - TD));
        float4 v = *(const float4*)src;
        v.x *= scale; v.y *= scale; v.z *= scale; v.w *= scale;
        *(float4*)&sQ[r * QP + d] = v;
    }

    unsigned long long acc2[8][2];
    float m[8], l[8];
    #pragma unroll
    for (int i = 0; i < 8; i++) {
        acc2[i][0] = 0ULL; acc2[i][1] = 0ULL;
        m[i] = -1e30f; l[i] = 0.0f;
    }

    for (int kt = 0; kt < TS / BK; kt++) {
        const int k0 = kt * BK;

        // ---- Load K tile into staging [c][d] (pitch 129) ----
        #pragma unroll
        for (int it = 0; it < (BK * TDK / 4) / NT; it++) {  // 8 iters
            int idx4 = tid + it * NT;
            int c = idx4 >> 5;
            int d = (idx4 & 31) << 2;
            const float* src = (d < TD) ? (Kb  + (size_t)(k0 + c) * TD + d)
                                        : (Kpb + (size_t)(k0 + c) * TD + (d - TD));
            float4 v = *(const float4*)src;
            float* dst = &stg[c * STP + d];
            dst[0] = v.x; dst[1] = v.y; dst[2] = v.z; dst[3] = v.w;
        }
        // ---- Load V tile [k][d] row-major ----
        #pragma unroll
        for (int it = 0; it < (BK * TD / 4) / NT; it++) {   // 4 iters
            int idx4 = tid + it * NT;
            int c = idx4 >> 4;
            int d = (idx4 & 15) << 2;
            *(float4*)&sV[c * VP + d] =
                *(const float4*)(Vb + (size_t)(k0 + c) * TD + d);
        }
        __syncthreads();

        // ---- Transpose staging -> sKT [d][c] (conflict-free both sides) ----
        #pragma unroll
        for (int it = 0; it < (BK * TDK) / NT; it++) {      // 32 iters
            int idx = tid + it * NT;
            int d = idx >> 6;
            int c = idx & 63;
            sKT[d * KTP + c] = stg[c * STP + d];
        }
        __syncthreads();

        // ---- S = Q @ K'^T  (8x4 per thread, f32x2 packed) ----
        unsigned long long s2[8][2];
        #pragma unroll
        for (int i = 0; i < 8; i++) { s2[i][0] = 0ULL; s2[i][1] = 0ULL; }

        #pragma unroll 2
        for (int k = 0; k < TDK; k += 4) {
            float4 qv[8];
            #pragma unroll
            for (int i = 0; i < 8; i++)
                qv[i] = *(const float4*)&sQ[(8 * ty + i) * QP + k];
            ulonglong2 kv[4];
            #pragma unroll
            for (int kk = 0; kk < 4; kk++)
                kv[kk] = *(const ulonglong2*)&sKT[(k + kk) * KTP + 4 * tx];
            #pragma unroll
            for (int i = 0; i < 8; i++) {
                const float* qf = (const float*)&qv[i];
                #pragma unroll
                for (int kk = 0; kk < 4; kk++) {
                    unsigned long long qb = pk2(qf[kk], qf[kk]);
                    s2[i][0] = fma2(qb, kv[kk].x, s2[i][0]);
                    s2[i][1] = fma2(qb, kv[kk].y, s2[i][1]);
                }
            }
        }

        // ---- Online softmax (row stats across 16 lanes / row) ----
        #pragma unroll
        for (int i = 0; i < 8; i++) {
            float v0, v1, v2, v3;
            upk2(s2[i][0], v0, v1);
            upk2(s2[i][1], v2, v3);
            float tm = fmaxf(fmaxf(v0, v1), fmaxf(v2, v3));
            tm = fmaxf(tm, __shfl_xor_sync(0xffffffffu, tm, 1));
            tm = fmaxf(tm, __shfl_xor_sync(0xffffffffu, tm, 2));
            tm = fmaxf(tm, __shfl_xor_sync(0xffffffffu, tm, 4));
            tm = fmaxf(tm, __shfl_xor_sync(0xffffffffu, tm, 8));
            float mn = fmaxf(m[i], tm);
            float alpha = __expf(m[i] - mn);
            m[i] = mn;
            float p0 = __expf(v0 - mn);
            float p1 = __expf(v1 - mn);
            float p2 = __expf(v2 - mn);
            float p3 = __expf(v3 - mn);
            float rs = (p0 + p1) + (p2 + p3);
            rs += __shfl_xor_sync(0xffffffffu, rs, 1);
            rs += __shfl_xor_sync(0xffffffffu, rs, 2);
            rs += __shfl_xor_sync(0xffffffffu, rs, 4);
            rs += __shfl_xor_sync(0xffffffffu, rs, 8);
            l[i] = l[i] * alpha + rs;
            unsigned long long a2 = pk2(alpha, alpha);
            acc2[i][0] = mul2(acc2[i][0], a2);
            acc2[i][1] = mul2(acc2[i][1], a2);
            float4 pv4 = make_float4(p0, p1, p2, p3);
            *(float4*)&sP[(8 * ty + i) * PP + 4 * tx] = pv4;
        }
        __syncthreads();

        // ---- O += P @ V (f32x2 packed) ----
        #pragma unroll 2
        for (int k = 0; k < BK; k += 4) {
            float4 pr[8];
            #pragma unroll
            for (int i = 0; i < 8; i++)
                pr[i] = *(const float4*)&sP[(8 * ty + i) * PP + k];
            ulonglong2 vv[4];
            #pragma unroll
            for (int kk = 0; kk < 4; kk++)
                vv[kk] = *(const ulonglong2*)&sV[(k + kk) * VP + 4 * tx];
            #pragma unroll
            for (int i = 0; i < 8; i++) {
                const float* pf = (const float*)&pr[i];
                #pragma unroll
                for (int kk = 0; kk < 4; kk++) {
                    unsigned long long pb = pk2(pf[kk], pf[kk]);
                    acc2[i][0] = fma2(pb, vv[kk].x, acc2[i][0]);
                    acc2[i][1] = fma2(pb, vv[kk].y, acc2[i][1]);
                }
            }
        }
        __syncthreads();
    }

    // ---- Epilogue: normalize and store ----
    #pragma unroll
    for (int i = 0; i < 8; i++) {
        float inv = 1.0f / l[i];
        float o0, o1, o2, o3;
        upk2(acc2[i][0], o0, o1);
        upk2(acc2[i][1], o2, o3);
        float4 o = make_float4(o0 * inv, o1 * inv, o2 * inv, o3 * inv);
        *(float4*)(Og + ((size_t)bh * TS + q0 + 8 * ty + i) * TD + 4 * tx) = o;
    }
}

extern "C" void kernel_launch(void* const* d_in, const int* in_sizes, int n_in,
                              void* d_out, int out_size)
{
    const float* Q  = (const float*)d_in[0];
    const float* K  = (const float*)d_in[1];
    const float* V  = (const float*)d_in[2];
    const float* Qp = (const float*)d_in[3];
    const float* Kp = (const float*)d_in[4];
    float* O = (float*)d_out;

    cudaFuncSetAttribute(sdpa_flash_f32x2_kernel,
                         cudaFuncAttributeMaxDynamicSharedMemorySize,
                         SM_FLOATS * (int)sizeof(float));

    dim3 grid(TS / BQ, TB * TH);   // (16, 32)
    sdpa_flash_f32x2_kernel<<<grid, NT, SM_FLOATS * sizeof(float)>>>(
        Q, K, V, Qp, Kp, O);
}

// round 8
// speedup vs baseline: 2.8610x; 2.8610x over previous
#include <cuda_runtime.h>
#include <cuda_bf16.h>
#include <cstdint>

// ---------------- problem constants ----------------
#define TSEQ 2048
#define TD   64
#define TDK  128            // combined head dim [Q|Qpos]
#define BQ   128            // q rows per CTA
#define BK   64             // kv rows per tile
#define NT   256            // 8 warps
#define NTILES (TSEQ/BK)    // 32

// ---------------- SMEM (bytes, dynamic) ----------------
// K tiles: [64][136] bf16 (pitch 272 B) ; V tiles: [64][72] bf16 (pitch 144 B)
#define KPITCH 272
#define VPITCH 144
#define SM_KH 0
#define SM_KL 17408
#define SM_VH 34816
#define SM_VL 44032
// Q staging (reused region): [128][136] bf16 hi at 0, lo at 34816
#define SM_QH 0
#define SM_QL 34816
#define SMEM_TOTAL 69632

__device__ __forceinline__ uint32_t smem_u32(const void* p) {
    uint32_t a;
    asm("{ .reg .u64 t; cvta.to.shared.u64 t, %1; cvt.u32.u64 %0, t; }" : "=r"(a) : "l"(p));
    return a;
}
// pack two fp32 -> bf16x2 (e0 -> low half, e1 -> high half)
__device__ __forceinline__ uint32_t cvt2bf(float e1, float e0) {
    uint32_t r;
    asm("cvt.rn.bf16x2.f32 %0, %1, %2;" : "=r"(r) : "f"(e1), "f"(e0));
    return r;
}

#define HMMA(d, a, b0, b1)                                                       \
    asm volatile("mma.sync.aligned.m16n8k16.row.col.f32.bf16.bf16.f32 "          \
        "{%0,%1,%2,%3}, {%4,%5,%6,%7}, {%8,%9}, {%0,%1,%2,%3};"                  \
        : "+f"((d)[0]), "+f"((d)[1]), "+f"((d)[2]), "+f"((d)[3])                 \
        : "r"((a)[0]), "r"((a)[1]), "r"((a)[2]), "r"((a)[3]), "r"(b0), "r"(b1))

#define LDSM4(r0, r1, r2, r3, addr)                                              \
    asm volatile("ldmatrix.sync.aligned.m8n8.x4.shared.b16 {%0,%1,%2,%3}, [%4];" \
        : "=r"(r0), "=r"(r1), "=r"(r2), "=r"(r3) : "r"(addr))

#define LDSM4T(r0, r1, r2, r3, addr)                                             \
    asm volatile("ldmatrix.sync.aligned.m8n8.x4.trans.shared.b16 {%0,%1,%2,%3}, [%4];" \
        : "=r"(r0), "=r"(r1), "=r"(r2), "=r"(r3) : "r"(addr))

// split one float4 into hi/lo bf16x2 pairs, 8B stores at byte offsets (no swizzle)
__device__ __forceinline__ void split_store(char* sm, uint32_t off_h, uint32_t off_l,
                                            float4 v) {
    uint32_t h01 = cvt2bf(v.y, v.x);
    uint32_t h23 = cvt2bf(v.w, v.z);
    float r0 = v.x - __uint_as_float(h01 << 16);
    float r1 = v.y - __uint_as_float(h01 & 0xFFFF0000u);
    float r2 = v.z - __uint_as_float(h23 << 16);
    float r3 = v.w - __uint_as_float(h23 & 0xFFFF0000u);
    *(uint2*)(sm + off_h) = make_uint2(h01, h23);
    *(uint2*)(sm + off_l) = make_uint2(cvt2bf(r1, r0), cvt2bf(r3, r2));
}

__global__ __launch_bounds__(NT, 1)
void sdpa_mma_kernel(const float* __restrict__ Qg,
                     const float* __restrict__ Kg,
                     const float* __restrict__ Vg,
                     const float* __restrict__ Qpg,
                     const float* __restrict__ Kpg,
                     float* __restrict__ Og)
{
    extern __shared__ char smem[];
    const uint32_t sbase = smem_u32(smem);

    const int tid  = threadIdx.x;
    const int wid  = tid >> 5;
    const int lane = tid & 31;

    const int bh = blockIdx.y;
    const int q0 = blockIdx.x * BQ;
    const size_t bh_off = (size_t)bh * TSEQ * TD;
    const float* Qb  = Qg  + bh_off;
    const float* Qpb = Qpg + bh_off;
    const float* Kb  = Kg  + bh_off;
    const float* Kpb = Kpg + bh_off;
    const float* Vb  = Vg  + bh_off;

    // ================= stage Q' (scaled), split hi/lo =================
    const float scale = 0.125f;
    #pragma unroll
    for (int it = 0; it < 16; it++) {
        int idx4 = tid + it * NT;
        int r = idx4 >> 5;                 // 128 rows, 32 float4 per row
        int c = (idx4 & 31) << 2;
        const float* src = (c < TD) ? (Qb + (size_t)(q0 + r) * TD + c)
                                    : (Qpb + (size_t)(q0 + r) * TD + (c - TD));
        float4 v = *(const float4*)src;
        v.x *= scale; v.y *= scale; v.z *= scale; v.w *= scale;
        uint32_t o = (uint32_t)r * KPITCH + (uint32_t)c * 2;
        split_store(smem, SM_QH + o, SM_QL + o, v);
    }
    __syncthreads();

    // ----- extract Q a-fragments (warp rows 16w .. 16w+15) -----
    uint32_t qh[8][4], ql[8][4];
    {
        uint32_t row = (uint32_t)(16 * wid) + (lane & 7) + ((lane >> 3) & 1) * 8;
        uint32_t base_r = row * KPITCH;
        uint32_t cshift = ((uint32_t)(lane >> 4)) * 16;   // +8 cols -> +16 B
        #pragma unroll
        for (int kk = 0; kk < 8; kk++) {
            uint32_t off = base_r + (uint32_t)kk * 32 + cshift;
            LDSM4(qh[kk][0], qh[kk][1], qh[kk][2], qh[kk][3], sbase + SM_QH + off);
            LDSM4(ql[kk][0], ql[kk][1], ql[kk][2], ql[kk][3], sbase + SM_QL + off);
        }
    }
    __syncthreads();   // staging region now reusable for K/V

    // ================= flash attention state =================
    float o_acc[8][4];
    #pragma unroll
    for (int i = 0; i < 8; i++)
        #pragma unroll
        for (int j = 0; j < 4; j++) o_acc[i][j] = 0.0f;
    float m0 = -1e30f, m1 = -1e30f, l0 = 0.0f, l1 = 0.0f;

    // precomputed ldmatrix lane addressing
    const uint32_t k_row  = (lane & 7) + ((lane >> 4) & 1) * 8;   // within 16-row pair
    const uint32_t k_kseg = ((lane >> 3) & 1) * 16;               // +8 cols -> +16 B
    const uint32_t v_row  = (lane & 7) + ((lane >> 3) & 1) * 8;
    const uint32_t v_col  = ((uint32_t)(lane >> 4)) * 16;         // +8 cols -> +16 B

    for (int kt = 0; kt < NTILES; kt++) {
        const int k0 = kt * BK;

        // ---- load K' tile [64 x 128], split hi/lo ----
        #pragma unroll
        for (int it = 0; it < 8; it++) {
            int idx4 = tid + it * NT;
            int r = idx4 >> 5;
            int c = (idx4 & 31) << 2;
            const float* src = (c < TD) ? (Kb + (size_t)(k0 + r) * TD + c)
                                        : (Kpb + (size_t)(k0 + r) * TD + (c - TD));
            float4 v = *(const float4*)src;
            uint32_t o = (uint32_t)r * KPITCH + (uint32_t)c * 2;
            split_store(smem, SM_KH + o, SM_KL + o, v);
        }
        // ---- load V tile [64 x 64], split hi/lo ----
        #pragma unroll
        for (int it = 0; it < 4; it++) {
            int idx4 = tid + it * NT;
            int r = idx4 >> 4;
            int c = (idx4 & 15) << 2;
            float4 v = *(const float4*)(Vb + (size_t)(k0 + r) * TD + c);
            uint32_t o = (uint32_t)r * VPITCH + (uint32_t)c * 2;
            split_store(smem, SM_VH + o, SM_VL + o, v);
        }
        __syncthreads();

        // ---- S = Qh*Kh + Qh*Kl + Ql*Kh  (16x64 per warp) ----
        float s[8][4];
        #pragma unroll
        for (int i = 0; i < 8; i++)
            #pragma unroll
            for (int j = 0; j < 4; j++) s[i][j] = 0.0f;

        #pragma unroll
        for (int kk = 0; kk < 8; kk++) {
            #pragma unroll
            for (int np = 0; np < 4; np++) {
                uint32_t off = (16u * np + k_row) * KPITCH + (uint32_t)kk * 32 + k_kseg;
                uint32_t h0, h1, h2, h3, e0, e1, e2, e3;
                LDSM4(h0, h1, h2, h3, sbase + SM_KH + off);
                LDSM4(e0, e1, e2, e3, sbase + SM_KL + off);
                HMMA(s[2 * np],     qh[kk], h0, h1);
                HMMA(s[2 * np],     ql[kk], h0, h1);
                HMMA(s[2 * np],     qh[kk], e0, e1);
                HMMA(s[2 * np + 1], qh[kk], h2, h3);
                HMMA(s[2 * np + 1], ql[kk], h2, h3);
                HMMA(s[2 * np + 1], qh[kk], e2, e3);
            }
        }

        // ---- online softmax (rows: lane/4 and lane/4+8) ----
        float tm0 = -1e30f, tm1 = -1e30f;
        #pragma unroll
        for (int i = 0; i < 8; i++) {
            tm0 = fmaxf(tm0, fmaxf(s[i][0], s[i][1]));
            tm1 = fmaxf(tm1, fmaxf(s[i][2], s[i][3]));
        }
        tm0 = fmaxf(tm0, __shfl_xor_sync(0xffffffffu, tm0, 1));
        tm0 = fmaxf(tm0, __shfl_xor_sync(0xffffffffu, tm0, 2));
        tm1 = fmaxf(tm1, __shfl_xor_sync(0xffffffffu, tm1, 1));
        tm1 = fmaxf(tm1, __shfl_xor_sync(0xffffffffu, tm1, 2));
        float mn0 = fmaxf(m0, tm0), mn1 = fmaxf(m1, tm1);
        float a0 = __expf(m0 - mn0), a1 = __expf(m1 - mn1);
        m0 = mn0; m1 = mn1;

        float rs0 = 0.0f, rs1 = 0.0f;
        uint32_t ph0[8], ph1[8], pl0[8], pl1[8];
        #pragma unroll
        for (int i = 0; i < 8; i++) {
            float p0 = __expf(s[i][0] - mn0);
            float p1 = __expf(s[i][1] - mn0);
            float p2 = __expf(s[i][2] - mn1);
            float p3 = __expf(s[i][3] - mn1);
            rs0 += p0 + p1; rs1 += p2 + p3;
            uint32_t h01 = cvt2bf(p1, p0);
            uint32_t h23 = cvt2bf(p3, p2);
            ph0[i] = h01; ph1[i] = h23;
            float r0 = p0 - __uint_as_float(h01 << 16);
            float r1 = p1 - __uint_as_float(h01 & 0xFFFF0000u);
            float r2 = p2 - __uint_as_float(h23 << 16);
            float r3 = p3 - __uint_as_float(h23 & 0xFFFF0000u);
            pl0[i] = cvt2bf(r1, r0);
            pl1[i] = cvt2bf(r3, r2);
        }
        rs0 += __shfl_xor_sync(0xffffffffu, rs0, 1);
        rs0 += __shfl_xor_sync(0xffffffffu, rs0, 2);
        rs1 += __shfl_xor_sync(0xffffffffu, rs1, 1);
        rs1 += __shfl_xor_sync(0xffffffffu, rs1, 2);
        l0 = l0 * a0 + rs0;
        l1 = l1 * a1 + rs1;

        // rescale O accumulators
        #pragma unroll
        for (int i = 0; i < 8; i++) {
            o_acc[i][0] *= a0; o_acc[i][1] *= a0;
            o_acc[i][2] *= a1; o_acc[i][3] *= a1;
        }

        // ---- O += Ph*Vh + Ph*Vl + Pl*Vh ----
        #pragma unroll
        for (int kk = 0; kk < 4; kk++) {
            uint32_t aH[4] = { ph0[2 * kk], ph1[2 * kk], ph0[2 * kk + 1], ph1[2 * kk + 1] };
            uint32_t aL[4] = { pl0[2 * kk], pl1[2 * kk], pl0[2 * kk + 1], pl1[2 * kk + 1] };
            #pragma unroll
            for (int np = 0; np < 4; np++) {
                uint32_t off = (16u * kk + v_row) * VPITCH + 32u * np + v_col;
                uint32_t h0, h1, h2, h3, e0, e1, e2, e3;
                LDSM4T(h0, h1, h2, h3, sbase + SM_VH + off);
                LDSM4T(e0, e1, e2, e3, sbase + SM_VL + off);
                HMMA(o_acc[2 * np],     aH, h0, h1);
                HMMA(o_acc[2 * np],     aL, h0, h1);
                HMMA(o_acc[2 * np],     aH, e0, e1);
                HMMA(o_acc[2 * np + 1], aH, h2, h3);
                HMMA(o_acc[2 * np + 1], aL, h2, h3);
                HMMA(o_acc[2 * np + 1], aH, e2, e3);
            }
        }
        __syncthreads();   // done with K/V smem before next iteration overwrites
    }

    // ================= epilogue =================
    float inv0 = 1.0f / l0, inv1 = 1.0f / l1;
    int row0 = 16 * wid + (lane >> 2);
    int row1 = row0 + 8;
    int colb = 2 * (lane & 3);
    size_t obase = ((size_t)bh * TSEQ + q0);
    #pragma unroll
    for (int i = 0; i < 8; i++) {
        int col = 8 * i + colb;
        *(float2*)(Og + (obase + row0) * TD + col) =
            make_float2(o_acc[i][0] * inv0, o_acc[i][1] * inv0);
        *(float2*)(Og + (obase + row1) * TD + col) =
            make_float2(o_acc[i][2] * inv1, o_acc[i][3] * inv1);
    }
}

extern "C" void kernel_launch(void* const* d_in, const int* in_sizes, int n_in,
                              void* d_out, int out_size)
{
    const float* Q  = (const float*)d_in[0];
    const float* K  = (const float*)d_in[1];
    const float* V  = (const float*)d_in[2];
    const float* Qp = (const float*)d_in[3];
    const float* Kp = (const float*)d_in[4];
    float* O = (float*)d_out;

    cudaFuncSetAttribute(sdpa_mma_kernel,
                         cudaFuncAttributeMaxDynamicSharedMemorySize, SMEM_TOTAL);

    dim3 grid(TSEQ / BQ, 2 * 16);   // (16, 32)
    sdpa_mma_kernel<<<grid, NT, SMEM_TOTAL>>>(Q, K, V, Qp, Kp, O);
}

// round 10
// speedup vs baseline: 3.3345x; 1.1655x over previous
#include <cuda_runtime.h>
#include <cuda_bf16.h>
#include <cstdint>

// ---------------- problem constants ----------------
#define TSEQ 2048
#define TD   64
#define TDK  128            // combined head dim [Q|Qpos]
#define BQ   128            // q rows per CTA
#define BK   64             // kv rows per tile
#define NT   256            // 8 warps
#define NTILES (TSEQ/BK)    // 32

// ---------------- SMEM (bytes, dynamic), double buffered ----------------
// per buffer: KH [64][136]bf16 @0, KL @17408, VH [64][72]bf16 @34816, VL @44032
#define KPITCH 272
#define VPITCH 144
#define SM_KH 0
#define SM_KL 17408
#define SM_VH 34816
#define SM_VL 44032
#define BUFSZ 53248
#define SMEM_TOTAL (2*BUFSZ)          // 106,496 B
// Q staging (prologue only, spans buffer region): hi @0, lo @34816
#define SM_QH 0
#define SM_QL 34816

__device__ __forceinline__ uint32_t smem_u32(const void* p) {
    uint32_t a;
    asm("{ .reg .u64 t; cvta.to.shared.u64 t, %1; cvt.u32.u64 %0, t; }" : "=r"(a) : "l"(p));
    return a;
}
// pack two fp32 -> bf16x2 (e0 -> low half, e1 -> high half)
__device__ __forceinline__ uint32_t cvt2bf(float e1, float e0) {
    uint32_t r;
    asm("cvt.rn.bf16x2.f32 %0, %1, %2;" : "=r"(r) : "f"(e1), "f"(e0));
    return r;
}

#define HMMA(d, a, b0, b1)                                                       \
    asm volatile("mma.sync.aligned.m16n8k16.row.col.f32.bf16.bf16.f32 "          \
        "{%0,%1,%2,%3}, {%4,%5,%6,%7}, {%8,%9}, {%0,%1,%2,%3};"                  \
        : "+f"((d)[0]), "+f"((d)[1]), "+f"((d)[2]), "+f"((d)[3])                 \
        : "r"((a)[0]), "r"((a)[1]), "r"((a)[2]), "r"((a)[3]), "r"(b0), "r"(b1))

#define LDSM4(r0, r1, r2, r3, addr)                                              \
    asm volatile("ldmatrix.sync.aligned.m8n8.x4.shared.b16 {%0,%1,%2,%3}, [%4];" \
        : "=r"(r0), "=r"(r1), "=r"(r2), "=r"(r3) : "r"(addr))

#define LDSM4T(r0, r1, r2, r3, addr)                                             \
    asm volatile("ldmatrix.sync.aligned.m8n8.x4.trans.shared.b16 {%0,%1,%2,%3}, [%4];" \
        : "=r"(r0), "=r"(r1), "=r"(r2), "=r"(r3) : "r"(addr))

// split one float4 into hi/lo bf16x2 pairs, 8B stores at byte offsets
__device__ __forceinline__ void split_store(char* sm, uint32_t off_h, uint32_t off_l,
                                            float4 v) {
    uint32_t h01 = cvt2bf(v.y, v.x);
    uint32_t h23 = cvt2bf(v.w, v.z);
    float r0 = v.x - __uint_as_float(h01 << 16);
    float r1 = v.y - __uint_as_float(h01 & 0xFFFF0000u);
    float r2 = v.z - __uint_as_float(h23 << 16);
    float r3 = v.w - __uint_as_float(h23 & 0xFFFF0000u);
    *(uint2*)(sm + off_h) = make_uint2(h01, h23);
    *(uint2*)(sm + off_l) = make_uint2(cvt2bf(r1, r0), cvt2bf(r3, r2));
}

__global__ __launch_bounds__(NT, 1)
void sdpa_mma_db_kernel(const float* __restrict__ Qg,
                        const float* __restrict__ Kg,
                        const float* __restrict__ Vg,
                        const float* __restrict__ Qpg,
                        const float* __restrict__ Kpg,
                        float* __restrict__ Og)
{
    extern __shared__ char smem[];
    const uint32_t sbase = smem_u32(smem);

    const int tid  = threadIdx.x;
    const int wid  = tid >> 5;
    const int lane = tid & 31;

    const int bh = blockIdx.y;
    const int q0 = blockIdx.x * BQ;
    const size_t bh_off = (size_t)bh * TSEQ * TD;
    const float* Qb  = Qg  + bh_off;
    const float* Qpb = Qpg + bh_off;
    const float* Kb  = Kg  + bh_off;
    const float* Kpb = Kpg + bh_off;
    const float* Vb  = Vg  + bh_off;

    // per-thread load coordinates (fixed across tiles)
    const int kr = tid >> 5;                 // K row group: 8 rows strided by 8
    const int kc = (tid & 31) << 2;          // K col (d) group
    const int vr = tid >> 4;                 // V row group: 16 rows strided by 16
    const int vc = (tid & 15) << 2;          // V col group

    // ================= stage Q' (scaled), split hi/lo =================
    const float scale = 0.125f;
    #pragma unroll
    for (int it = 0; it < 16; it++) {
        int idx4 = tid + it * NT;
        int r = idx4 >> 5;
        int c = (idx4 & 31) << 2;
        const float* src = (c < TD) ? (Qb + (size_t)(q0 + r) * TD + c)
                                    : (Qpb + (size_t)(q0 + r) * TD + (c - TD));
        float4 v = *(const float4*)src;
        v.x *= scale; v.y *= scale; v.z *= scale; v.w *= scale;
        uint32_t o = (uint32_t)r * KPITCH + (uint32_t)c * 2;
        split_store(smem, SM_QH + o, SM_QL + o, v);
    }
    __syncthreads();

    // ----- issue tile-0 prefetch LDGs (don't touch smem) -----
    float4 kreg[8], vreg[4];
    #pragma unroll
    for (int it = 0; it < 8; it++) {
        int r = kr + it * 8;
        int c = kc;
        const float* src = (c < TD) ? (Kb + (size_t)r * TD + c)
                                    : (Kpb + (size_t)r * TD + (c - TD));
        kreg[it] = *(const float4*)src;
    }
    #pragma unroll
    for (int it = 0; it < 4; it++)
        vreg[it] = *(const float4*)(Vb + (size_t)(vr + it * 16) * TD + vc);

    // ----- extract Q a-fragments (warp rows 16w .. 16w+15) -----
    uint32_t qh[8][4], ql[8][4];
    {
        uint32_t row = (uint32_t)(16 * wid) + (lane & 7) + ((lane >> 3) & 1) * 8;
        uint32_t base_r = row * KPITCH;
        uint32_t cshift = ((uint32_t)(lane >> 4)) * 16;
        #pragma unroll
        for (int kk = 0; kk < 8; kk++) {
            uint32_t off = base_r + (uint32_t)kk * 32 + cshift;
            LDSM4(qh[kk][0], qh[kk][1], qh[kk][2], qh[kk][3], sbase + SM_QH + off);
            LDSM4(ql[kk][0], ql[kk][1], ql[kk][2], ql[kk][3], sbase + SM_QL + off);
        }
    }
    __syncthreads();   // Q staging region free

    // ----- STS tile 0 into buffer 0 -----
    #pragma unroll
    for (int it = 0; it < 8; it++) {
        uint32_t o = (uint32_t)(kr + it * 8) * KPITCH + (uint32_t)kc * 2;
        split_store(smem, SM_KH + o, SM_KL + o, kreg[it]);
    }
    #pragma unroll
    for (int it = 0; it < 4; it++) {
        uint32_t o = (uint32_t)(vr + it * 16) * VPITCH + (uint32_t)vc * 2;
        split_store(smem, SM_VH + o, SM_VL + o, vreg[it]);
    }
    __syncthreads();

    // ================= flash attention state =================
    float o_acc[8][4];
    #pragma unroll
    for (int i = 0; i < 8; i++)
        #pragma unroll
        for (int j = 0; j < 4; j++) o_acc[i][j] = 0.0f;
    float m0 = -1e30f, m1 = -1e30f, l0 = 0.0f, l1 = 0.0f;

    const uint32_t k_row  = (lane & 7) + ((lane >> 4) & 1) * 8;
    const uint32_t k_kseg = ((lane >> 3) & 1) * 16;
    const uint32_t v_row  = (lane & 7) + ((lane >> 3) & 1) * 8;
    const uint32_t v_col  = ((uint32_t)(lane >> 4)) * 16;

    for (int kt = 0; kt < NTILES; kt++) {
        const uint32_t bb = (kt & 1) ? (uint32_t)BUFSZ : 0u;   // compute buffer
        const uint32_t nb = BUFSZ - bb;                         // fill buffer

        // ---- prefetch LDGs for tile kt+1 (overlap with compute below) ----
        if (kt + 1 < NTILES) {
            const int k0n = (kt + 1) * BK;
            #pragma unroll
            for (int it = 0; it < 8; it++) {
                int r = k0n + kr + it * 8;
                const float* src = (kc < TD) ? (Kb + (size_t)r * TD + kc)
                                             : (Kpb + (size_t)r * TD + (kc - TD));
                kreg[it] = *(const float4*)src;
            }
            #pragma unroll
            for (int it = 0; it < 4; it++)
                vreg[it] = *(const float4*)(Vb + (size_t)(k0n + vr + it * 16) * TD + vc);
        }

        // ---- S = Qh*Kh + Qh*Kl + Ql*Kh  (16x64 per warp) ----
        float s[8][4];
        #pragma unroll
        for (int i = 0; i < 8; i++)
            #pragma unroll
            for (int j = 0; j < 4; j++) s[i][j] = 0.0f;

        #pragma unroll
        for (int kk = 0; kk < 8; kk++) {
            #pragma unroll
            for (int np = 0; np < 4; np++) {
                uint32_t off = bb + (16u * np + k_row) * KPITCH + (uint32_t)kk * 32 + k_kseg;
                uint32_t h0, h1, h2, h3, e0, e1, e2, e3;
                LDSM4(h0, h1, h2, h3, sbase + SM_KH + off);
                LDSM4(e0, e1, e2, e3, sbase + SM_KL + off);
                HMMA(s[2 * np],     qh[kk], h0, h1);
                HMMA(s[2 * np],     ql[kk], h0, h1);
                HMMA(s[2 * np],     qh[kk], e0, e1);
                HMMA(s[2 * np + 1], qh[kk], h2, h3);
                HMMA(s[2 * np + 1], ql[kk], h2, h3);
                HMMA(s[2 * np + 1], qh[kk], e2, e3);
            }
        }

        // ---- online softmax (rows: lane/4 and lane/4+8) ----
        float tm0 = -1e30f, tm1 = -1e30f;
        #pragma unroll
        for (int i = 0; i < 8; i++) {
            tm0 = fmaxf(tm0, fmaxf(s[i][0], s[i][1]));
            tm1 = fmaxf(tm1, fmaxf(s[i][2], s[i][3]));
        }
        tm0 = fmaxf(tm0, __shfl_xor_sync(0xffffffffu, tm0, 1));
        tm0 = fmaxf(tm0, __shfl_xor_sync(0xffffffffu, tm0, 2));
        tm1 = fmaxf(tm1, __shfl_xor_sync(0xffffffffu, tm1, 1));
        tm1 = fmaxf(tm1, __shfl_xor_sync(0xffffffffu, tm1, 2));
        float mn0 = fmaxf(m0, tm0), mn1 = fmaxf(m1, tm1);
        float a0 = __expf(m0 - mn0), a1 = __expf(m1 - mn1);
        m0 = mn0; m1 = mn1;

        float rs0 = 0.0f, rs1 = 0.0f;
        uint32_t ph0[8], ph1[8], pl0[8], pl1[8];
        #pragma unroll
        for (int i = 0; i < 8; i++) {
            float p0 = __expf(s[i][0] - mn0);
            float p1 = __expf(s[i][1] - mn0);
            float p2 = __expf(s[i][2] - mn1);
            float p3 = __expf(s[i][3] - mn1);
            rs0 += p0 + p1; rs1 += p2 + p3;
            uint32_t h01 = cvt2bf(p1, p0);
            uint32_t h23 = cvt2bf(p3, p2);
            ph0[i] = h01; ph1[i] = h23;
            float r0 = p0 - __uint_as_float(h01 << 16);
            float r1 = p1 - __uint_as_float(h01 & 0xFFFF0000u);
            float r2 = p2 - __uint_as_float(h23 << 16);
            float r3 = p3 - __uint_as_float(h23 & 0xFFFF0000u);
            pl0[i] = cvt2bf(r1, r0);
            pl1[i] = cvt2bf(r3, r2);
        }
        rs0 += __shfl_xor_sync(0xffffffffu, rs0, 1);
        rs0 += __shfl_xor_sync(0xffffffffu, rs0, 2);
        rs1 += __shfl_xor_sync(0xffffffffu, rs1, 1);
        rs1 += __shfl_xor_sync(0xffffffffu, rs1, 2);
        l0 = l0 * a0 + rs0;
        l1 = l1 * a1 + rs1;

        #pragma unroll
        for (int i = 0; i < 8; i++) {
            o_acc[i][0] *= a0; o_acc[i][1] *= a0;
            o_acc[i][2] *= a1; o_acc[i][3] *= a1;
        }

        // ---- O += Ph*Vh + Ph*Vl + Pl*Vh ----
        #pragma unroll
        for (int kk = 0; kk < 4; kk++) {
            uint32_t aH[4] = { ph0[2 * kk], ph1[2 * kk], ph0[2 * kk + 1], ph1[2 * kk + 1] };
            uint32_t aL[4] = { pl0[2 * kk], pl1[2 * kk], pl0[2 * kk + 1], pl1[2 * kk + 1] };
            #pragma unroll
            for (int np = 0; np < 4; np++) {
                uint32_t off = bb + (16u * kk + v_row) * VPITCH + 32u * np + v_col;
                uint32_t h0, h1, h2, h3, e0, e1, e2, e3;
                LDSM4T(h0, h1, h2, h3, sbase + SM_VH + off);
                LDSM4T(e0, e1, e2, e3, sbase + SM_VL + off);
                HMMA(o_acc[2 * np],     aH, h0, h1);
                HMMA(o_acc[2 * np],     aL, h0, h1);
                HMMA(o_acc[2 * np],     aH, e0, e1);
                HMMA(o_acc[2 * np + 1], aH, h2, h3);
                HMMA(o_acc[2 * np + 1], aL, h2, h3);
                HMMA(o_acc[2 * np + 1], aH, e2, e3);
            }
        }

        // ---- STS prefetched tile kt+1 into the other buffer ----
        if (kt + 1 < NTILES) {
            #pragma unroll
            for (int it = 0; it < 8; it++) {
                uint32_t o = nb + (uint32_t)(kr + it * 8) * KPITCH + (uint32_t)kc * 2;
                split_store(smem, SM_KH + o, SM_KL + o, kreg[it]);
            }
            #pragma unroll
            for (int it = 0; it < 4; it++) {
                uint32_t o = nb + (uint32_t)(vr + it * 16) * VPITCH + (uint32_t)vc * 2;
                split_store(smem, SM_VH + o, SM_VL + o, vreg[it]);
            }
        }
        __syncthreads();
    }

    // ================= epilogue =================
    float inv0 = 1.0f / l0, inv1 = 1.0f / l1;
    int row0 = 16 * wid + (lane >> 2);
    int row1 = row0 + 8;
    int colb = 2 * (lane & 3);
    size_t obase = ((size_t)bh * TSEQ + q0);
    #pragma unroll
    for (int i = 0; i < 8; i++) {
        int col = 8 * i + colb;
        *(float2*)(Og + (obase + row0) * TD + col) =
            make_float2(o_acc[i][0] * inv0, o_acc[i][1] * inv0);
        *(float2*)(Og + (obase + row1) * TD + col) =
            make_float2(o_acc[i][2] * inv1, o_acc[i][3] * inv1);
    }
}

extern "C" void kernel_launch(void* const* d_in, const int* in_sizes, int n_in,
                              void* d_out, int out_size)
{
    const float* Q  = (const float*)d_in[0];
    const float* K  = (const float*)d_in[1];
    const float* V  = (const float*)d_in[2];
    const float* Qp = (const float*)d_in[3];
    const float* Kp = (const float*)d_in[4];
    float* O = (float*)d_out;

    cudaFuncSetAttribute(sdpa_mma_db_kernel,
                         cudaFuncAttributeMaxDynamicSharedMemorySize, SMEM_TOTAL);

    dim3 grid(TSEQ / BQ, 2 * 16);   // (16, 32)
    sdpa_mma_db_kernel<<<grid, NT, SMEM_TOTAL>>>(Q, K, V, Qp, Kp, O);
}